// round 2
// baseline (speedup 1.0000x reference)
#include <cuda_runtime.h>
#include <cstdint>
#include <cstddef>

// Problem constants (fixed shapes for this dataset)
#define NN     4096     // N*N
#define CC     256      // feature dim
#define BB     32       // batch (videos)
#define SS     64       // sentences
#define TPB    128      // threads per block in score kernel
#define RP     2        // proposals per thread
#define TILE   (TPB*RP) // proposals per block (256)
#define NTILES (NN/TILE)// worst-case tiles (16)
#define NPBLK  (BB*NTILES)

#define INV_T 10.0f     // 1 / 0.1
#define EPSN  1e-12f

// ---------------- device scratch (no allocations allowed) ----------------
__device__ int   g_flat[NN];          // compacted proposal -> flat (i*N+j)
__device__ int   g_P;                 // number of valid proposals
__device__ int   g_scatter[SS];       // sentence -> video index
__device__ float g_sf[SS*CC];         // normalized sentence feats [s][c]
__device__ float g_sfT[CC*SS];        // normalized sentence feats [c][s]
__device__ float g_partial[NPBLK*SS]; // per-block partial neg-exp sums
__device__ float g_negsum[SS];        // inter-query neg sums
__device__ int   g_pstar[SS];         // per-sentence argmax proposal (flat idx)
__device__ float g_A[SS*SS];          // A[s][t] = dot(topk_video[s], sf[t])

// packed fp32x2 helpers (SASS FFMA2 — only reachable via PTX)
__device__ __forceinline__ void ffma2(unsigned long long& acc,
                                      unsigned long long w,
                                      unsigned long long v) {
    asm("fma.rn.f32x2 %0, %1, %2, %0;" : "+l"(acc) : "l"(w), "l"(v));
}
__device__ __forceinline__ unsigned long long pack2(float x) {
    unsigned long long r;
    asm("mov.b64 %0, {%1, %1};" : "=l"(r) : "r"(__float_as_uint(x)));
    return r;
}
__device__ __forceinline__ float unpack_lo(unsigned long long u) {
    return __uint_as_float((unsigned)(u & 0xffffffffu));
}
__device__ __forceinline__ float unpack_hi(unsigned long long u) {
    return __uint_as_float((unsigned)(u >> 32));
}

// ---------------- setup: compact mask + scatter indices ----------------
__global__ void setup_kernel(const unsigned char* __restrict__ mask,
                             const int* __restrict__ num_targets) {
    __shared__ int wsum[32];
    __shared__ int mode_s;
    int t = threadIdx.x;                  // 1024 threads, 4 entries each
    if (t == 0) mode_s = (mask[1] != 0);  // byte-bool vs 4-byte encoding
    __syncthreads();
    int mode = mode_s;

    int pred[4], cnt = 0;
#pragma unroll
    for (int k = 0; k < 4; k++) {
        int idx = t * 4 + k;
        int m = mode ? (mask[idx] != 0)
                     : (((const int*)mask)[idx] != 0);
        pred[k] = m; cnt += m;
    }
    int lane = t & 31, w = t >> 5;
    int inc = cnt;
#pragma unroll
    for (int off = 1; off < 32; off <<= 1) {
        int y = __shfl_up_sync(0xffffffffu, inc, off);
        if (lane >= off) inc += y;
    }
    if (lane == 31) wsum[w] = inc;
    __syncthreads();
    if (w == 0) {
        int v = wsum[lane];
#pragma unroll
        for (int off = 1; off < 32; off <<= 1) {
            int y = __shfl_up_sync(0xffffffffu, v, off);
            if (lane >= off) v += y;
        }
        wsum[lane] = v;
    }
    __syncthreads();
    int base = (w ? wsum[w - 1] : 0) + inc - cnt;
#pragma unroll
    for (int k = 0; k < 4; k++) {
        if (pred[k]) g_flat[base++] = t * 4 + k;
    }
    if (t == blockDim.x - 1) g_P = wsum[31];

    if (t == 0) {
        int off = 0;
        for (int b = 0; b < BB && off < SS; b++) {
            int n = num_targets[b];
            for (int k = 0; k < n && off < SS; k++) g_scatter[off++] = b;
        }
    }
}

// ---------------- normalize sentence features (row + transposed copies) --
__global__ void norm_sents(const float* __restrict__ sents) {
    int s = blockIdx.x, c = threadIdx.x;   // SS blocks x CC threads
    __shared__ float sm[CC];
    float x = sents[s * CC + c];
    sm[c] = x * x;
    __syncthreads();
    for (int st = CC / 2; st > 0; st >>= 1) {
        if (c < st) sm[c] += sm[c + st];
        __syncthreads();
    }
    float inv = 1.0f / fmaxf(sqrtf(sm[0]), EPSN);
    float v = x * inv;
    g_sf[s * CC + c]  = v;
    g_sfT[c * SS + s] = v;
}

// ---------------- per-sentence argmax over gathered iou ----------------
__global__ void argmax_k(const float* __restrict__ iou) {
    int s = blockIdx.x, t = threadIdx.x;   // SS blocks x 256 threads
    int P = g_P;
    __shared__ float bv[256];
    __shared__ int   bi[256];
    float best = -1e30f;
    int bp = 1 << 30;
    for (int p = t; p < P; p += 256) {
        float v = iou[s * NN + g_flat[p]];
        if (v > best) { best = v; bp = p; }   // ascending p => first max kept
    }
    bv[t] = best; bi[t] = bp;
    __syncthreads();
    for (int st = 128; st > 0; st >>= 1) {
        if (t < st) {
            if (bv[t + st] > bv[t] || (bv[t + st] == bv[t] && bi[t + st] < bi[t])) {
                bv[t] = bv[t + st]; bi[t] = bi[t + st];
            }
        }
        __syncthreads();
    }
    if (t == 0) g_pstar[s] = g_flat[bi[0]];
}

// ---------------- main fused score kernel ----------------
// Block = (p-tile of 256 proposals, video b). Thread owns TWO proposals
// (p0 = base+tid, p1 = base+TPB+tid for coalescing). Inner product with all
// 64 sentences packed as 32 f32x2 accumulators per proposal (FFMA2).
// Normalization folded in post-hoc via rsqrt(sum v^2).
#define SCORE_SMEM_FLOATS (CC*SS + SS*4 + SS)
__global__ void score_kernel(const float* __restrict__ video,
                             const float* __restrict__ iou) {
    const int P = g_P;
    const int tile = blockIdx.x;
    if (tile * TILE >= P) return;          // dead padding tile: skip all work

    extern __shared__ float smem[];
    float* sfT  = smem;                 // [CC][SS]
    float* red  = smem + CC * SS;       // SS*4
    int*   scat = (int*)(red + SS * 4); // SS

    const int b = blockIdx.y;

    for (int i = threadIdx.x; i < CC * SS / 4; i += TPB)
        ((float4*)sfT)[i] = ((const float4*)g_sfT)[i];
    if (threadIdx.x < SS) scat[threadIdx.x] = g_scatter[threadIdx.x];
    __syncthreads();

    const int p0 = tile * TILE + (int)threadIdx.x;
    const int p1 = p0 + TPB;
    const bool va = (p0 < P);
    const bool vb = (p1 < P);
    const int g0 = va ? g_flat[p0] : 0;
    const int g1 = vb ? g_flat[p1] : 0;
    const float* vp0 = video + (size_t)b * CC * NN + g0;
    const float* vp1 = video + (size_t)b * CC * NN + g1;

    unsigned long long acc0[SS/2], acc1[SS/2];
#pragma unroll
    for (int j = 0; j < SS/2; j++) { acc0[j] = 0ull; acc1[j] = 0ull; }
    float ssq0 = 0.0f, ssq1 = 0.0f;

    const ulonglong2* swT = (const ulonglong2*)sfT;

#pragma unroll 1
    for (int c = 0; c < CC; c++) {
        float v0 = va ? vp0[(size_t)c * NN] : 0.0f;
        float v1 = vb ? vp1[(size_t)c * NN] : 0.0f;
        ssq0 = fmaf(v0, v0, ssq0);
        ssq1 = fmaf(v1, v1, ssq1);
        unsigned long long vv0 = pack2(v0);
        unsigned long long vv1 = pack2(v1);
        const ulonglong2* row = swT + c * (SS/4);
#pragma unroll
        for (int j = 0; j < SS/4; j++) {
            ulonglong2 w = row[j];
            ffma2(acc0[2*j + 0], w.x, vv0);
            ffma2(acc0[2*j + 1], w.y, vv0);
            ffma2(acc1[2*j + 0], w.x, vv1);
            ffma2(acc1[2*j + 1], w.y, vv1);
        }
    }

    const float inv0 = va ? rsqrtf(fmaxf(ssq0, 1e-24f)) * INV_T : 0.0f;
    const float inv1 = vb ? rsqrtf(fmaxf(ssq1, 1e-24f)) * INV_T : 0.0f;

    const int lane = threadIdx.x & 31;
    const int wrp  = threadIdx.x >> 5;
#pragma unroll 1
    for (int j = 0; j < SS/2; j++) {
        float e = 0.0f;
#pragma unroll
        for (int h = 0; h < 2; h++) {
            int s = 2*j + h;
            bool same = (scat[s] == b);
            if (va) {
                float iv = same ? iou[s * NN + g0] : 0.0f;
                if (!(same && iv > 0.5f)) {
                    float sc = (h ? unpack_hi(acc0[j]) : unpack_lo(acc0[j])) * inv0;
                    e += __expf(sc);
                }
            }
            if (vb) {
                float iv = same ? iou[s * NN + g1] : 0.0f;
                if (!(same && iv > 0.5f)) {
                    float sc = (h ? unpack_hi(acc1[j]) : unpack_lo(acc1[j])) * inv1;
                    e += __expf(sc);
                }
            }
            // warp-reduce for sentence s
#pragma unroll
            for (int off = 16; off; off >>= 1)
                e += __shfl_down_sync(0xffffffffu, e, off);
            if (lane == 0) red[s * 4 + wrp] = e;
            e = 0.0f;
        }
    }
    __syncthreads();
    if (threadIdx.x < SS) {
        int s = threadIdx.x;
        g_partial[(b * NTILES + tile) * SS + s] =
            red[s * 4 + 0] + red[s * 4 + 1] + red[s * 4 + 2] + red[s * 4 + 3];
    }
}

// ---------------- deterministic reduction of partials ----------------
__global__ void reduce_neg() {
    int s = blockIdx.x;            // SS blocks x 256 threads
    int t = threadIdx.x;
    int used = (g_P + TILE - 1) / TILE;   // live tiles per video
    __shared__ float sm[256];
    float sum = 0.0f;
    for (int i = t; i < BB * NTILES; i += 256) {
        int tl = i % NTILES;
        if (tl < used) sum += g_partial[i * SS + s];
    }
    sm[t] = sum;
    __syncthreads();
    for (int st = 128; st > 0; st >>= 1) {
        if (t < st) sm[t] += sm[t + st];
        __syncthreads();
    }
    if (t == 0) g_negsum[s] = sm[0];
}

// ---------------- A[s][t] = dot(normalized topk proposal of s, sf[t]) ----
__global__ void topk_dots(const float* __restrict__ video) {
    int s = blockIdx.x, t = threadIdx.x;   // SS blocks x 256 threads
    __shared__ float tv[CC];
    __shared__ float rs[CC];
    int b = g_scatter[s];
    int g = g_pstar[s];
    float v = video[((size_t)(b * CC + t)) * NN + g];
    rs[t] = v * v;
    __syncthreads();
    for (int st = 128; st > 0; st >>= 1) {
        if (t < st) rs[t] += rs[t + st];
        __syncthreads();
    }
    float inv = 1.0f / fmaxf(sqrtf(rs[0]), EPSN);
    tv[t] = v * inv;
    __syncthreads();
    int lane = t & 31, wrp = t >> 5;
    for (int q = wrp; q < SS; q += 8) {
        float d = 0.0f;
        for (int c = lane; c < CC; c += 32) d += g_sf[q * CC + c] * tv[c];
#pragma unroll
        for (int off = 16; off; off >>= 1)
            d += __shfl_down_sync(0xffffffffu, d, off);
        if (lane == 0) g_A[s * SS + q] = d;
    }
}

// ---------------- final losses ----------------
__global__ void finalize(float* __restrict__ out) {
    __shared__ float l1[SS], l2[SS];
    int s = threadIdx.x;   // SS threads
    float pos = g_A[s * SS + s];
    float nsv = 0.0f;
    for (int u = 0; u < SS; u++)
        if (u != s) nsv += expf(g_A[s * SS + u] * INV_T);
    float pe = expf(pos * INV_T);
    float lv = -(pos * INV_T - logf(pe + nsv));
    float lq = -(pos * INV_T - logf(pe + g_negsum[s]));
    l1[s] = lv; l2[s] = lq;
    __syncthreads();
    for (int st = 32; st > 0; st >>= 1) {
        if (s < st) { l1[s] += l1[s + st]; l2[s] += l2[s + st]; }
        __syncthreads();
    }
    if (s == 0) {
        out[0] = l1[0] / (float)SS;  // loss_inter_video
        out[1] = l2[0] / (float)SS;  // loss_inter_query
    }
}

// ---------------- launcher ----------------
extern "C" void kernel_launch(void* const* d_in, const int* in_sizes, int n_in,
                              void* d_out, int out_size) {
    const float*         video = (const float*)d_in[0];         // [B,C,N,N]
    const float*         sents = (const float*)d_in[1];         // [S,C]
    const int*           ntgt  = (const int*)d_in[2];           // [B]
    const float*         iou   = (const float*)d_in[3];         // [S,N,N]
    const unsigned char* mask  = (const unsigned char*)d_in[4]; // [N,N] bool
    float* out = (float*)d_out;

    const int smem_bytes = SCORE_SMEM_FLOATS * (int)sizeof(float);
    cudaFuncSetAttribute(score_kernel,
                         cudaFuncAttributeMaxDynamicSharedMemorySize, smem_bytes);

    setup_kernel<<<1, 1024>>>(mask, ntgt);
    norm_sents<<<SS, CC>>>(sents);
    argmax_k<<<SS, 256>>>(iou);
    dim3 grid(NTILES, BB);
    score_kernel<<<grid, TPB, smem_bytes>>>(video, iou);
    reduce_neg<<<SS, 256>>>();
    topk_dots<<<SS, 256>>>(video);
    finalize<<<1, SS>>>(out);
}

// round 3
// speedup vs baseline: 1.5988x; 1.5988x over previous
#include <cuda_runtime.h>
#include <cstdint>
#include <cstddef>

// Problem constants (fixed shapes for this dataset)
#define NN     4096     // N*N
#define CC     256      // feature dim
#define BB     32       // batch (videos)
#define SS     64       // sentences
#define PT     128      // proposals per block tile
#define KC     32       // K-chunk staged in smem
#define TPB2   256      // threads in score kernel
#define MAXT   (NN/PT)  // worst-case tiles (32)

#define INV_T 10.0f     // 1 / 0.1
#define EPSN  1e-12f

// ---------------- device scratch (no allocations allowed) ----------------
__device__ int   g_flat[NN];          // compacted proposal -> flat (i*N+j)
__device__ int   g_P;                 // number of valid proposals
__device__ int   g_scatter[SS];       // sentence -> video index
__device__ float g_sf[SS*CC];         // normalized sentence feats [s][c]
__device__ float g_sfT[CC*SS];        // normalized sentence feats [c][s]
__device__ float g_partial[BB*MAXT*SS]; // per-block partial neg-exp sums
__device__ float g_negsum[SS];        // inter-query neg sums
__device__ int   g_pstar[SS];         // per-sentence argmax proposal (flat idx)
__device__ float g_A[SS*SS];          // A[s][t] = dot(topk_video[s], sf[t])

// packed fp32x2 helpers (SASS FFMA2 — only reachable via PTX)
__device__ __forceinline__ void ffma2(unsigned long long& acc,
                                      unsigned long long w,
                                      unsigned long long v) {
    asm("fma.rn.f32x2 %0, %1, %2, %0;" : "+l"(acc) : "l"(w), "l"(v));
}
__device__ __forceinline__ unsigned long long pack2(float x) {
    unsigned long long r;
    asm("mov.b64 %0, {%1, %1};" : "=l"(r) : "r"(__float_as_uint(x)));
    return r;
}
__device__ __forceinline__ float unpack_lo(unsigned long long u) {
    return __uint_as_float((unsigned)(u & 0xffffffffu));
}
__device__ __forceinline__ float unpack_hi(unsigned long long u) {
    return __uint_as_float((unsigned)(u >> 32));
}

// ---------------- setup: compact mask + scatter indices ----------------
__global__ void setup_kernel(const unsigned char* __restrict__ mask,
                             const int* __restrict__ num_targets) {
    __shared__ int wsum[32];
    __shared__ int mode_s;
    int t = threadIdx.x;                  // 1024 threads, 4 entries each
    if (t == 0) mode_s = (mask[1] != 0);  // byte-bool vs 4-byte encoding
    __syncthreads();
    int mode = mode_s;

    int pred[4], cnt = 0;
#pragma unroll
    for (int k = 0; k < 4; k++) {
        int idx = t * 4 + k;
        int m = mode ? (mask[idx] != 0)
                     : (((const int*)mask)[idx] != 0);
        pred[k] = m; cnt += m;
    }
    int lane = t & 31, w = t >> 5;
    int inc = cnt;
#pragma unroll
    for (int off = 1; off < 32; off <<= 1) {
        int y = __shfl_up_sync(0xffffffffu, inc, off);
        if (lane >= off) inc += y;
    }
    if (lane == 31) wsum[w] = inc;
    __syncthreads();
    if (w == 0) {
        int v = wsum[lane];
#pragma unroll
        for (int off = 1; off < 32; off <<= 1) {
            int y = __shfl_up_sync(0xffffffffu, v, off);
            if (lane >= off) v += y;
        }
        wsum[lane] = v;
    }
    __syncthreads();
    int base = (w ? wsum[w - 1] : 0) + inc - cnt;
#pragma unroll
    for (int k = 0; k < 4; k++) {
        if (pred[k]) g_flat[base++] = t * 4 + k;
    }
    if (t == blockDim.x - 1) g_P = wsum[31];

    if (t == 0) {
        int off = 0;
        for (int b = 0; b < BB && off < SS; b++) {
            int n = num_targets[b];
            for (int k = 0; k < n && off < SS; k++) g_scatter[off++] = b;
        }
    }
}

// ---------------- normalize sentence features (row + transposed copies) --
__global__ void norm_sents(const float* __restrict__ sents) {
    int s = blockIdx.x, c = threadIdx.x;   // SS blocks x CC threads
    __shared__ float sm[CC];
    float x = sents[s * CC + c];
    sm[c] = x * x;
    __syncthreads();
    for (int st = CC / 2; st > 0; st >>= 1) {
        if (c < st) sm[c] += sm[c + st];
        __syncthreads();
    }
    float inv = 1.0f / fmaxf(sqrtf(sm[0]), EPSN);
    float v = x * inv;
    g_sf[s * CC + c]  = v;
    g_sfT[c * SS + s] = v;
}

// ---------------- per-sentence argmax over gathered iou ----------------
__global__ void argmax_k(const float* __restrict__ iou) {
    int s = blockIdx.x, t = threadIdx.x;   // SS blocks x 256 threads
    int P = g_P;
    __shared__ float bv[256];
    __shared__ int   bi[256];
    float best = -1e30f;
    int bp = 1 << 30;
    for (int p = t; p < P; p += 256) {
        float v = iou[s * NN + g_flat[p]];
        if (v > best) { best = v; bp = p; }   // ascending p => first max kept
    }
    bv[t] = best; bi[t] = bp;
    __syncthreads();
    for (int st = 128; st > 0; st >>= 1) {
        if (t < st) {
            if (bv[t + st] > bv[t] || (bv[t + st] == bv[t] && bi[t + st] < bi[t])) {
                bv[t] = bv[t + st]; bi[t] = bi[t + st];
            }
        }
        __syncthreads();
    }
    if (t == 0) g_pstar[s] = g_flat[bi[0]];
}

// ---------------- main fused score kernel: register-tiled GEMM ----------
// Block tile: 128 proposals x 64 sentences, K chunked by 32 through smem.
// 256 threads as (tp in [0,16), ts in [0,16)): thread computes an 8p x 4s
// register tile with proposal pairs packed as f32x2 (FFMA2). Sentence
// values are pre-duplicated into smem pairs so the inner loop has NO pack
// instructions: per k = 4 LDS.128 + 16 FFMA2 (64 MACs).
__global__ __launch_bounds__(TPB2)
void score_kernel(const float* __restrict__ video,
                  const float* __restrict__ iou) {
    const int P = g_P;
    const int tile = blockIdx.x;
    const int tbase = tile * PT;
    if (tbase >= P) return;                // dead padding tile
    const int b = blockIdx.y;

    __shared__ float vt[KC][PT];                   // 16 KB video tile [k][p]
    __shared__ unsigned long long sfd[KC][SS];     // 16 KB dup sentence pairs
    __shared__ float ssq_part[TPB2];
    __shared__ float inorm[PT];
    __shared__ float red[SS][16];
    __shared__ int   scat[SS];
    __shared__ int   gflat_s[PT];                  // -1 sentinel for padding

    const int tid = threadIdx.x;
    if (tid < SS) scat[tid] = g_scatter[tid];
    if (tid < PT) gflat_s[tid] = (tbase + tid < P) ? g_flat[tbase + tid] : -1;

    const int tp = tid & 15;        // proposal group: 8 proposals
    const int ts = tid >> 4;        // sentence group: 4 sentences
    const size_t vbase = (size_t)b * CC * NN;

    unsigned long long acc[4][4];   // [ppair][s]
#pragma unroll
    for (int j = 0; j < 4; j++)
#pragma unroll
        for (int i = 0; i < 4; i++) acc[j][i] = 0ull;
    float ssq = 0.0f;

    __syncthreads();                // gflat_s ready for loaders

    for (int ch = 0; ch < CC / KC; ch++) {
        const int c0 = ch * KC;
        // stage video tile (gathered, mostly-coalesced)
#pragma unroll
        for (int i = 0; i < (KC * PT) / TPB2; i++) {       // 16
            int idx = tid + i * TPB2;
            int c = idx >> 7, p = idx & (PT - 1);
            int g = gflat_s[p];
            vt[c][p] = (g >= 0) ? __ldg(&video[vbase + (size_t)(c0 + c) * NN + g]) : 0.0f;
        }
        // stage duplicated sentence pairs
#pragma unroll
        for (int i = 0; i < (KC * SS) / TPB2; i++) {       // 8
            int idx = tid + i * TPB2;
            int k = idx >> 6, s = idx & (SS - 1);
            sfd[k][s] = pack2(g_sfT[(c0 + k) * SS + s]);
        }
        __syncthreads();

        // deterministic ssq partial: thread -> proposal tid&127, half tid>>7
        {
            int pp = tid & (PT - 1);
            int h  = tid >> 7;
#pragma unroll
            for (int c = 0; c < KC / 2; c++) {
                float v = vt[h * (KC / 2) + c][pp];
                ssq = fmaf(v, v, ssq);
            }
        }

        // inner product: FMA-pipe bound
#pragma unroll 8
        for (int k = 0; k < KC; k++) {
            ulonglong2 va = *reinterpret_cast<const ulonglong2*>(&vt[k][tp * 8]);
            ulonglong2 vb2 = *reinterpret_cast<const ulonglong2*>(&vt[k][tp * 8 + 4]);
            ulonglong2 sa = *reinterpret_cast<const ulonglong2*>(&sfd[k][ts * 4]);
            ulonglong2 sb = *reinterpret_cast<const ulonglong2*>(&sfd[k][ts * 4 + 2]);
            ffma2(acc[0][0], sa.x, va.x);
            ffma2(acc[0][1], sa.y, va.x);
            ffma2(acc[0][2], sb.x, va.x);
            ffma2(acc[0][3], sb.y, va.x);
            ffma2(acc[1][0], sa.x, va.y);
            ffma2(acc[1][1], sa.y, va.y);
            ffma2(acc[1][2], sb.x, va.y);
            ffma2(acc[1][3], sb.y, va.y);
            ffma2(acc[2][0], sa.x, vb2.x);
            ffma2(acc[2][1], sa.y, vb2.x);
            ffma2(acc[2][2], sb.x, vb2.x);
            ffma2(acc[2][3], sb.y, vb2.x);
            ffma2(acc[3][0], sa.x, vb2.y);
            ffma2(acc[3][1], sa.y, vb2.y);
            ffma2(acc[3][2], sb.x, vb2.y);
            ffma2(acc[3][3], sb.y, vb2.y);
        }
        __syncthreads();
    }

    // finalize norms (deterministic 2-term combine)
    ssq_part[tid] = ssq;
    __syncthreads();
    if (tid < PT) {
        float tot = ssq_part[tid] + ssq_part[tid + PT];
        inorm[tid] = rsqrtf(fmaxf(tot, 1e-24f)) * INV_T;
    }
    __syncthreads();

    float invv[8];
    int   gg[8];
#pragma unroll
    for (int jj = 0; jj < 8; jj++) {
        invv[jj] = inorm[tp * 8 + jj];
        gg[jj]   = gflat_s[tp * 8 + jj];
    }

#pragma unroll
    for (int i = 0; i < 4; i++) {
        int s = ts * 4 + i;
        bool same = (scat[s] == b);
        float esum = 0.0f;
#pragma unroll
        for (int j = 0; j < 4; j++) {
            float sc0 = unpack_lo(acc[j][i]) * invv[2 * j];
            float sc1 = unpack_hi(acc[j][i]) * invv[2 * j + 1];
            int g0 = gg[2 * j], g1 = gg[2 * j + 1];
            if (g0 >= 0 && !(same && iou[s * NN + g0] > 0.5f)) esum += __expf(sc0);
            if (g1 >= 0 && !(same && iou[s * NN + g1] > 0.5f)) esum += __expf(sc1);
        }
        red[s][tp] = esum;
    }
    __syncthreads();
    if (tid < SS) {
        float t = 0.0f;
#pragma unroll
        for (int q = 0; q < 16; q++) t += red[tid][q];
        g_partial[(b * MAXT + tile) * SS + tid] = t;
    }
}

// ---------------- deterministic reduction of partials ----------------
__global__ void reduce_neg() {
    int s = blockIdx.x;            // SS blocks x 256 threads
    int t = threadIdx.x;
    int used = (g_P + PT - 1) / PT;   // live tiles per video
    __shared__ float sm[256];
    float sum = 0.0f;
    for (int i = t; i < BB * MAXT; i += 256) {
        int tl = i % MAXT;
        if (tl < used) sum += g_partial[i * SS + s];
    }
    sm[t] = sum;
    __syncthreads();
    for (int st = 128; st > 0; st >>= 1) {
        if (t < st) sm[t] += sm[t + st];
        __syncthreads();
    }
    if (t == 0) g_negsum[s] = sm[0];
}

// ---------------- A[s][t] = dot(normalized topk proposal of s, sf[t]) ----
__global__ void topk_dots(const float* __restrict__ video) {
    int s = blockIdx.x, t = threadIdx.x;   // SS blocks x 256 threads
    __shared__ float tv[CC];
    __shared__ float rs[CC];
    int b = g_scatter[s];
    int g = g_pstar[s];
    float v = video[((size_t)(b * CC + t)) * NN + g];
    rs[t] = v * v;
    __syncthreads();
    for (int st = 128; st > 0; st >>= 1) {
        if (t < st) rs[t] += rs[t + st];
        __syncthreads();
    }
    float inv = 1.0f / fmaxf(sqrtf(rs[0]), EPSN);
    tv[t] = v * inv;
    __syncthreads();
    int lane = t & 31, wrp = t >> 5;
    for (int q = wrp; q < SS; q += 8) {
        float d = 0.0f;
        for (int c = lane; c < CC; c += 32) d += g_sf[q * CC + c] * tv[c];
#pragma unroll
        for (int off = 16; off; off >>= 1)
            d += __shfl_down_sync(0xffffffffu, d, off);
        if (lane == 0) g_A[s * SS + q] = d;
    }
}

// ---------------- final losses ----------------
__global__ void finalize(float* __restrict__ out) {
    __shared__ float l1[SS], l2[SS];
    int s = threadIdx.x;   // SS threads
    float pos = g_A[s * SS + s];
    float nsv = 0.0f;
    for (int u = 0; u < SS; u++)
        if (u != s) nsv += expf(g_A[s * SS + u] * INV_T);
    float pe = expf(pos * INV_T);
    float lv = -(pos * INV_T - logf(pe + nsv));
    float lq = -(pos * INV_T - logf(pe + g_negsum[s]));
    l1[s] = lv; l2[s] = lq;
    __syncthreads();
    for (int st = 32; st > 0; st >>= 1) {
        if (s < st) { l1[s] += l1[s + st]; l2[s] += l2[s + st]; }
        __syncthreads();
    }
    if (s == 0) {
        out[0] = l1[0] / (float)SS;  // loss_inter_video
        out[1] = l2[0] / (float)SS;  // loss_inter_query
    }
}

// ---------------- launcher ----------------
extern "C" void kernel_launch(void* const* d_in, const int* in_sizes, int n_in,
                              void* d_out, int out_size) {
    const float*         video = (const float*)d_in[0];         // [B,C,N,N]
    const float*         sents = (const float*)d_in[1];         // [S,C]
    const int*           ntgt  = (const int*)d_in[2];           // [B]
    const float*         iou   = (const float*)d_in[3];         // [S,N,N]
    const unsigned char* mask  = (const unsigned char*)d_in[4]; // [N,N] bool
    float* out = (float*)d_out;

    setup_kernel<<<1, 1024>>>(mask, ntgt);
    norm_sents<<<SS, CC>>>(sents);
    argmax_k<<<SS, 256>>>(iou);
    dim3 grid(MAXT, BB);
    score_kernel<<<grid, TPB2>>>(video, iou);
    reduce_neg<<<SS, 256>>>();
    topk_dots<<<SS, 256>>>(video);
    finalize<<<1, SS>>>(out);
}